// round 17
// baseline (speedup 1.0000x reference)
#include <cuda_runtime.h>
#include <cuda_fp16.h>
#include <cstdint>
#include <cstddef>

// ============================================================================
// EGNN layer: h' = h + MLP_u([h, scatter_add(MLP_m([h_s, h_r, dist]))])
//
// Layer-1 of the edge MLP is linear in gathered features -> node-level GEMMs
// P = h@W1a^T, Q = h@W1b^T, stored FP16. Edge kernel: half gather -> half2
// layer-1 + silu -> fp16 MMA (2Mx4N warp tiles, A via ldmatrix.x4, W2 from
// pre-packed lane-ordered fragments in two K-phases) -> silu -> fp16 staged
// tile -> float4 atomic scatter.
// ============================================================================

#define DD 128
#define NMAX 50176  // >= N = 50000

__device__ __align__(16) __half g_Ph[(size_t)NMAX * DD];
__device__ __align__(16) __half g_Qh[(size_t)NMAX * DD];
__device__ __align__(16) float  g_agg[(size_t)NMAX * DD];
__device__ __align__(16) float  g_u1[(size_t)NMAX * DD];
// W2 fp16 B-fragments, lane-ordered: uint4 index = w*256 + i*32 + lane,
// holding fragment values v = i*4 + {0..3};  v = nt*16 + kc*2 + j,
// where w = old 1Mx2N warp id (cols [16w,16w+16)).
__device__ uint4 g_W2frag[8 * 8 * 32];

__device__ __forceinline__ float* resolve_buf(int code, const float* ext) {
    switch (code) {
        case 1: return (float*)g_Ph;   // fp16 payload, cast at use
        case 2: return (float*)g_Qh;   // fp16 payload, cast at use
        case 3: return g_agg;
        case 4: return g_u1;
        default: return (float*)ext;
    }
}

// silu(x) = 0.5x(1 + tanh(x/2)) -- single MUFU
__device__ __forceinline__ float silu_f(float x) {
    float t;
    asm("tanh.approx.f32 %0, %1;" : "=f"(t) : "f"(0.5f * x));
    return 0.5f * x * (1.f + t);
}
__device__ __forceinline__ float2 silu2_f(float x0, float x1) {
    __half2 ph = __floats2half2_rn(0.5f * x0, 0.5f * x1);
    uint32_t pu = *(uint32_t*)&ph, tu;
    asm("tanh.approx.f16x2 %0, %1;" : "=r"(tu) : "r"(pu));
    float2 tf = __half22float2(*(__half2*)&tu);
    return make_float2(0.5f * x0 * (1.f + tf.x), 0.5f * x1 * (1.f + tf.y));
}
__device__ __forceinline__ __half2 silu_h2(__half2 x) {
    __half2 hx = __hmul2(x, __float2half2_rn(0.5f));
    uint32_t hu = *(uint32_t*)&hx, tu;
    asm("tanh.approx.f16x2 %0, %1;" : "=r"(tu) : "r"(hu));
    __half2 th = *(__half2*)&tu;
    return __hmul2(hx, __hadd2(__float2half2_rn(1.f), th));
}
__device__ __forceinline__ float tf32r(float x) {
    uint32_t u;
    asm("cvt.rna.tf32.f32 %0, %1;" : "=r"(u) : "f"(x));
    return __uint_as_float(u);
}
__device__ __forceinline__ void mma8(float* c, const uint32_t* a, const uint32_t* b) {
    asm volatile(
        "mma.sync.aligned.m16n8k8.row.col.f32.tf32.tf32.f32 "
        "{%0,%1,%2,%3},{%4,%5,%6,%7},{%8,%9},{%0,%1,%2,%3};\n"
        : "+f"(c[0]), "+f"(c[1]), "+f"(c[2]), "+f"(c[3])
        : "r"(a[0]), "r"(a[1]), "r"(a[2]), "r"(a[3]), "r"(b[0]), "r"(b[1]));
}
__device__ __forceinline__ void mma16(float* c, const uint32_t* a, const uint32_t* b) {
    asm volatile(
        "mma.sync.aligned.m16n8k16.row.col.f32.f16.f16.f32 "
        "{%0,%1,%2,%3},{%4,%5,%6,%7},{%8,%9},{%0,%1,%2,%3};\n"
        : "+f"(c[0]), "+f"(c[1]), "+f"(c[2]), "+f"(c[3])
        : "r"(a[0]), "r"(a[1]), "r"(a[2]), "r"(a[3]), "r"(b[0]), "r"(b[1]));
}

// ============================================================================
// Prep: pack W2 (fp32 [128][128]) into lane-ordered fp16 mma B-fragments.
// Flat u32 index t = w*1024 + i*128 + ln*4 + c.
// Decode: c = t&3, ln = (t>>2)&31, i = (t>>7)&7, w = t>>10.
// v = i*4 + c; nt = v>>4, kc = (v>>1)&7, j = v&1;
// n = w*16 + nt*8 + (ln>>2), kh = kc*16 + (ln&3)*2 + j*8
// value = half2(W2[n][kh], W2[n][kh+1])   (R13/R16-proven fragment layout)
// ============================================================================
__global__ void prep_w2(const float* __restrict__ W2) {
    int t = blockIdx.x * 256 + threadIdx.x;   // 0..8191
    if (t >= 8192) return;
    int c  = t & 3;
    int ln = (t >> 2) & 31;
    int i  = (t >> 7) & 7;
    int w  = t >> 10;
    int v  = i * 4 + c;
    int nt = v >> 4;
    int kc = (v >> 1) & 7;
    int j  = v & 1;
    int n  = w * 16 + nt * 8 + (ln >> 2);
    int kh = kc * 16 + (ln & 3) * 2 + j * 8;
    __half2 h = __floats2half2_rn(W2[(size_t)n * 128 + kh],
                                  W2[(size_t)n * 128 + kh + 1]);
    ((uint32_t*)g_W2frag)[t] = *(uint32_t*)&h;
}

// ============================================================================
// Node-level GEMM (tf32): out[M,128] = epi( sum_p A_p[M,128] @ B_p^T )
// mode 0: raw fp32; 1: silu(acc+bias); 2: acc+bias+resid; 3: raw fp16 out.
// ============================================================================
__global__ __launch_bounds__(256) void gemm_node(
    const float* __restrict__ A0e, int a0c,
    const float* __restrict__ B0, int ldb0,
    int a1c, const float* __restrict__ B1, int ldb1,
    const float* __restrict__ bias, const float* __restrict__ resid,
    float* __restrict__ oute, int outc, int M, int mode)
{
    __shared__ float As[128][36];
    __shared__ float Bs[128][36];
    int tid = threadIdx.x;
    int warp = tid >> 5, ln = tid & 31;
    int m0 = blockIdx.x * 128;

    const float* A0 = resolve_buf(a0c, A0e);
    const float* A1 = (a1c == 0) ? nullptr : resolve_buf(a1c, nullptr);
    float* out = resolve_buf(outc, oute);

    float acc[16][4];
#pragma unroll
    for (int i = 0; i < 16; ++i) {
        acc[i][0] = 0.f; acc[i][1] = 0.f; acc[i][2] = 0.f; acc[i][3] = 0.f;
    }

    for (int p = 0; p < 2; ++p) {
        const float* A = p ? A1 : A0;
        const float* B = p ? B1 : B0;
        int ldb = p ? ldb1 : ldb0;
        if (!A) continue;
        for (int k0 = 0; k0 < 128; k0 += 32) {
#pragma unroll
            for (int i = 0; i < 4; ++i) {
                int r = (tid >> 3) + i * 32;
                int c = (tid & 7) * 4;
                float4 v = make_float4(0.f, 0.f, 0.f, 0.f);
                int gr = m0 + r;
                if (gr < M) v = *(const float4*)(A + (size_t)gr * 128 + k0 + c);
                v.x = tf32r(v.x); v.y = tf32r(v.y); v.z = tf32r(v.z); v.w = tf32r(v.w);
                *(float4*)&As[r][c] = v;
            }
#pragma unroll
            for (int i = 0; i < 4; ++i) {
                int n = (tid >> 3) + i * 32;
                int c = (tid & 7) * 4;
                const float* bp = B + (size_t)n * ldb + k0 + c;
                Bs[n][c + 0] = tf32r(bp[0]);
                Bs[n][c + 1] = tf32r(bp[1]);
                Bs[n][c + 2] = tf32r(bp[2]);
                Bs[n][c + 3] = tf32r(bp[3]);
            }
            __syncthreads();

            int srow = warp * 16 + (ln >> 2);
            int scol = ln & 3;
#pragma unroll
            for (int kk = 0; kk < 4; ++kk) {
                uint32_t a[4];
                a[0] = __float_as_uint(As[srow][kk * 8 + scol]);
                a[1] = __float_as_uint(As[srow + 8][kk * 8 + scol]);
                a[2] = __float_as_uint(As[srow][kk * 8 + scol + 4]);
                a[3] = __float_as_uint(As[srow + 8][kk * 8 + scol + 4]);
#pragma unroll
                for (int nt = 0; nt < 16; ++nt) {
                    uint32_t b[2];
                    b[0] = __float_as_uint(Bs[nt * 8 + (ln >> 2)][kk * 8 + scol]);
                    b[1] = __float_as_uint(Bs[nt * 8 + (ln >> 2)][kk * 8 + scol + 4]);
                    mma8(acc[nt], a, b);
                }
            }
            __syncthreads();
        }
    }

    int r0 = m0 + warp * 16 + (ln >> 2);
    int c0 = (ln & 3) * 2;
#pragma unroll
    for (int nt = 0; nt < 16; ++nt) {
        int col = nt * 8 + c0;
#pragma unroll
        for (int h8 = 0; h8 < 2; ++h8) {
            int row = r0 + h8 * 8;
            if (row >= M) continue;
            float v0 = acc[nt][h8 * 2 + 0];
            float v1 = acc[nt][h8 * 2 + 1];
            if (mode == 3) {
                __half2 hv = __floats2half2_rn(v0, v1);
                *(__half2*)((__half*)out + (size_t)row * 128 + col) = hv;
            } else {
                if (mode == 1) {
                    v0 = silu_f(v0 + bias[col]);
                    v1 = silu_f(v1 + bias[col + 1]);
                } else if (mode == 2) {
                    v0 = v0 + bias[col]     + resid[(size_t)row * 128 + col];
                    v1 = v1 + bias[col + 1] + resid[(size_t)row * 128 + col + 1];
                }
                out[(size_t)row * 128 + col]     = v0;
                out[(size_t)row * 128 + col + 1] = v1;
            }
        }
    }
}

// ============================================================================
// Edge kernel: 64 edges/block, 256 threads, warps tiled 2M x 4N
// (warp = rows [32mq,32mq+32) x cols [32nq,32nq+32)). fp16 mma m16n8k16.
// A via ldmatrix.x4; W2 fragments loaded in TWO K-phases (32 live B regs);
// Ms staged fp16; float4 atomic scatter (proven epilogue).
// ============================================================================
#define AS_LD 136   // half stride: 272B rows; ldmatrix phases conflict-free

__global__ __launch_bounds__(256) void edge_kernel(
    const float* __restrict__ coords,
    const int* __restrict__ ei,     // int32 (JAX downcasts int64)
    const float* __restrict__ W1, const float* __restrict__ b1,
    const float* __restrict__ b2,
    int E)
{
    __shared__ __align__(16) char buf[64 * AS_LD * 2];  // 17408 B, aliased
    __shared__ int     s_sh[64];
    __shared__ int     r_sh[64];
    __shared__ float   dist_sh[64];
    __shared__ __half2 b1h[64];
    __shared__ __half2 w1ch[64];
    __shared__ float   b2s[128];

    half (*As)[AS_LD]  = (half(*)[AS_LD])buf;
    half (*Msh)[AS_LD] = (half(*)[AS_LD])buf;   // reused after MMA

    int tid = threadIdx.x;
    int warp = tid >> 5, ln = tid & 31;
    int mq = warp >> 2;          // 0..1 : rows [32mq, 32mq+32)
    int nq = warp & 3;           // 0..3 : cols [32nq, 32nq+32)
    int g = ln >> 2, q = ln & 3;
    int e0 = blockIdx.x * 64;

    // meta
    if (tid < 64) {
        int e = e0 + tid;
        int s = 0, r = -1;
        float d = 0.f;
        if (e < E) {
            s = ei[e];
            r = ei[(size_t)E + e];
            float dx = coords[s * 3 + 0] - coords[r * 3 + 0];
            float dy = coords[s * 3 + 1] - coords[r * 3 + 1];
            float dz = coords[s * 3 + 2] - coords[r * 3 + 2];
            d = sqrtf(dx * dx + dy * dy + dz * dz);
        }
        s_sh[tid] = s; r_sh[tid] = r; dist_sh[tid] = d;
        b1h[tid]  = __floats2half2_rn(b1[2 * tid], b1[2 * tid + 1]);
        w1ch[tid] = __floats2half2_rn(W1[(size_t)(2 * tid) * 257 + 256],
                                      W1[(size_t)(2 * tid + 1) * 257 + 256]);
    }
    if (tid < 128) b2s[tid] = b2[tid];
    __syncthreads();

    // gather (fp16) + layer-1 (half2) + silu -> As
#pragma unroll
    for (int it = 0; it < 8; ++it) {
        int idx = tid + it * 256;
        int i = idx >> 5;
        int j = (idx & 31) * 4;          // half index, multiple of 4
        int s = s_sh[i], r = r_sh[i];
        uint2 pk = make_uint2(0u, 0u);
        if (r >= 0) {
            __half2 d2 = __float2half2_rn(dist_sh[i]);
            uint2 pv = *(const uint2*)(g_Ph + (size_t)s * 128 + j);
            uint2 qv = *(const uint2*)(g_Qh + (size_t)r * 128 + j);
            __half2 p0 = *(__half2*)&pv.x, p1 = *(__half2*)&pv.y;
            __half2 q0 = *(__half2*)&qv.x, q1 = *(__half2*)&qv.y;
            int jh = j >> 1;
            __half2 x0 = __hadd2(__hadd2(p0, q0), b1h[jh]);
            x0 = __hfma2(d2, w1ch[jh], x0);
            __half2 x1 = __hadd2(__hadd2(p1, q1), b1h[jh + 1]);
            x1 = __hfma2(d2, w1ch[jh + 1], x1);
            __half2 a0 = silu_h2(x0);
            __half2 a1 = silu_h2(x1);
            pk = make_uint2(*(uint32_t*)&a0, *(uint32_t*)&a1);
        }
        *(uint2*)&As[i][j] = pk;
    }
    __syncthreads();

    // MMA: acc[mt][nt4] = rows [32mq+16mt,+16) x cols [32nq+8nt4,+8), K=128.
    // B fragments for col group nq = old-warp sets {2nq, 2nq+1}; loaded in
    // two K-phases so only 32 B regs are live at once.
    float acc[2][4][4];
#pragma unroll
    for (int mt = 0; mt < 2; ++mt)
#pragma unroll
        for (int nt = 0; nt < 4; ++nt) {
            acc[mt][nt][0] = 0.f; acc[mt][nt][1] = 0.f;
            acc[mt][nt][2] = 0.f; acc[mt][nt][3] = 0.f;
        }

#pragma unroll
    for (int p = 0; p < 2; ++p) {
        // load phase-p fragments: bflat[nt4*8 + kcl*2 + j]
        uint32_t bflat[32];
#pragma unroll
        for (int ow = 0; ow < 2; ++ow)
#pragma unroll
            for (int nt = 0; nt < 2; ++nt)
#pragma unroll
                for (int ii = 0; ii < 2; ++ii) {
                    uint4 t = g_W2frag[(2 * nq + ow) * 256 +
                                       (nt * 4 + p * 2 + ii) * 32 + ln];
                    int base = (ow * 2 + nt) * 8 + ii * 4;
                    bflat[base + 0] = t.x; bflat[base + 1] = t.y;
                    bflat[base + 2] = t.z; bflat[base + 3] = t.w;
                }
#pragma unroll
        for (int kcl = 0; kcl < 4; ++kcl) {
            int kc = p * 4 + kcl;
            uint32_t a[2][4];
#pragma unroll
            for (int mt = 0; mt < 2; ++mt) {
                int lrow = mq * 32 + mt * 16 + (ln & 15);
                int lcol = kc * 16 + (ln >> 4) * 8;
                uint32_t addr = (uint32_t)__cvta_generic_to_shared(&As[lrow][lcol]);
                asm volatile(
                    "ldmatrix.sync.aligned.m8n8.x4.shared.b16 {%0,%1,%2,%3}, [%4];"
                    : "=r"(a[mt][0]), "=r"(a[mt][1]), "=r"(a[mt][2]), "=r"(a[mt][3])
                    : "r"(addr));
            }
#pragma unroll
            for (int mt = 0; mt < 2; ++mt)
#pragma unroll
                for (int nt4 = 0; nt4 < 4; ++nt4)
                    mma16(acc[mt][nt4], a[mt], &bflat[nt4 * 8 + kcl * 2]);
        }
    }
    __syncthreads();  // As reads done; buf becomes Msh

    // stage m = silu(acc + b2) into Msh (fp16); warp tiles disjoint
#pragma unroll
    for (int mt = 0; mt < 2; ++mt) {
#pragma unroll
        for (int h8 = 0; h8 < 2; ++h8) {
            int rowi = mq * 32 + mt * 16 + h8 * 8 + g;
#pragma unroll
            for (int nt4 = 0; nt4 < 4; ++nt4) {
                int col = nq * 32 + nt4 * 8 + q * 2;
                float2 v = silu2_f(acc[mt][nt4][h8 * 2 + 0] + b2s[col],
                                   acc[mt][nt4][h8 * 2 + 1] + b2s[col + 1]);
                __half2 hv = __floats2half2_rn(v.x, v.y);
                *(__half2*)&Msh[rowi][col] = hv;
            }
        }
    }
    __syncthreads();

    // scatter: warp w -> rows [8w, 8w+8); one float4 atomic per row per lane
#pragma unroll
    for (int rr = 0; rr < 8; ++rr) {
        int row = warp * 8 + rr;
        int r = r_sh[row];
        if (r < 0) continue;
        uint2 hw = *(const uint2*)&Msh[row][ln * 4];
        float2 f0 = __half22float2(*(__half2*)&hw.x);
        float2 f1 = __half22float2(*(__half2*)&hw.y);
        float4 v = make_float4(f0.x, f0.y, f1.x, f1.y);
        atomicAdd((float4*)(g_agg + (size_t)r * 128 + ln * 4), v);
    }
}

__global__ void zero_agg(int n4) {
    int i = blockIdx.x * 256 + threadIdx.x;
    if (i < n4) ((float4*)g_agg)[i] = make_float4(0.f, 0.f, 0.f, 0.f);
}

// ============================================================================
// Host launch: kernel launches ONLY (graph-capture safe).
// ============================================================================
extern "C" void kernel_launch(void* const* d_in, const int* in_sizes, int n_in,
                              void* d_out, int out_size)
{
    const float* h_ptr  = (const float*)d_in[0];
    const float* coords = (const float*)d_in[1];
    const int*   ei     = (const int*)d_in[2];   // int32 (JAX downcasts int64)
    const float* W1     = (const float*)d_in[3];
    const float* b1     = (const float*)d_in[4];
    const float* W2     = (const float*)d_in[5];
    const float* b2     = (const float*)d_in[6];
    const float* U1     = (const float*)d_in[7];
    const float* c1     = (const float*)d_in[8];
    const float* U2     = (const float*)d_in[9];
    const float* c2     = (const float*)d_in[10];

    int N = in_sizes[0] / 128;
    int E = in_sizes[2] / 2;
    int mt = (N + 127) / 128;

    prep_w2<<<32, 256>>>(W2);

    // P = h @ W1[:, :128]^T ; Q = h @ W1[:, 128:256]^T  -> fp16 buffers
    gemm_node<<<mt, 256>>>(h_ptr, 0, W1, 257, 0, nullptr, 0,
                           nullptr, nullptr, nullptr, 1, N, 3);
    gemm_node<<<mt, 256>>>(h_ptr, 0, W1 + 128, 257, 0, nullptr, 0,
                           nullptr, nullptr, nullptr, 2, N, 3);

    int n4 = N * 32;  // N*128/4
    zero_agg<<<(n4 + 255) / 256, 256>>>(n4);

    edge_kernel<<<(E + 63) / 64, 256>>>(coords, ei, W1, b1, b2, E);

    // u1 = silu(h @ U1a^T + agg @ U1b^T + c1)
    gemm_node<<<mt, 256>>>(h_ptr, 0, U1, 256, 3, U1 + 128, 256,
                           c1, nullptr, nullptr, 4, N, 1);
    // out = h + u1 @ U2^T + c2
    gemm_node<<<mt, 256>>>(nullptr, 4, U2, 128, 0, nullptr, 0,
                           c2, h_ptr, (float*)d_out, 0, N, 2);
}